// round 16
// baseline (speedup 1.0000x reference)
#include <cuda_runtime.h>
#include <cuda_bf16.h>
#include <cuda_fp16.h>
#include <stdint.h>
#include <math.h>

// Problem constants
#define Bq   64
#define Tq   128
#define Eq   300
#define Hq   512
#define Cq   256
#define Mq   512
#define RPS  (Bq*Tq)      // 8192
#define NROWS (2*RPS)     // 16384
#define G4H  (4*Hq)       // 2048
#define D2H  (2*Hq)       // 1024
#define NCTA 128          // 64 per direction
#define KE   304

// -------- scratch ------------------------------------------------------------
__device__ float d_xW[2][NROWS][G4H];    // gate-interleaved [(j>>1)*8 + g*2 + (j&1)]
__device__ float d_P[NROWS][Cq];
__device__ float d_r[2][Bq][D2H];
__device__ __half d_Wh16[2][G4H][Hq];                // fp16 Whh
// h state (fp16) in mma-A-fragment-major layout:
// [parity][dir][mblock(8)][ktile(32)][lane(32)][slot(4)]  (u32 = half2)
__device__ uint32_t d_h16f[2][2][8][32][32][4];
__device__ __half d_xh16[NROWS][KE];                 // fp16 gathered embeddings
__device__ __half d_Wih16[2*G4H][KE];                // fp16 Wih (both dirs)
__device__ float d_biasC[2*G4H];
__device__ __half d_Hof[NROWS][D2H];                 // fp16 Hout (attn path)
__device__ __half d_S1Wh[Cq][D2H];                   // fp16 S1W
__device__ unsigned d_flags[2][64];                  // per-CTA arrive flags
__device__ unsigned g_epoch2[2];

// ---- helpers -----------------------------------------------------------------
__device__ __forceinline__ float fsigmoid(float x) { return __fdividef(1.f, 1.f + __expf(-x)); }
__device__ __forceinline__ float ftanh(float x)    { return 1.f - __fdividef(2.f, 1.f + __expf(2.f * x)); }
__device__ __forceinline__ uint32_t pack2h(float a, float b) {
    __half2 h = __floats2half2_rn(a, b);
    return *(uint32_t*)&h;
}

// ---------------- fused preamble: flags, h0 seed, Whh/S1W fp16 -----------------
__global__ void prep_all(const float* __restrict__ s1_h0, const float* __restrict__ s2_h0,
                         const float* __restrict__ Whh_f, const float* __restrict__ Whh_b,
                         const float* __restrict__ S1W) {
    int idx = blockIdx.x * blockDim.x + threadIdx.x;
    if (idx < 2) g_epoch2[idx] = 0;
    if (idx < 128) d_flags[idx >> 6][idx & 63] = 0;
    // h0 -> fragment slab (parity 0)
    if (idx < 2 * 128 * (Hq / 2)) {
        int jj  = idx % (Hq / 2);
        int j   = jj * 2;
        int m   = (idx / (Hq / 2)) % 128;
        int dir = idx / ((Hq / 2) * 128);
        int seq = m >> 6, b = m & 63;
        const float* h0 = seq ? s2_h0 : s1_h0;
        uint32_t v = pack2h(h0[(dir * Bq + b) * Hq + j], h0[(dir * Bq + b) * Hq + j + 1]);
        int mb   = m >> 4;
        int kt   = j >> 4;
        int lane = (m & 7) * 4 + ((j >> 1) & 3);
        int slot = ((j & 15) >> 3) * 2 + ((m & 15) >> 3);
        d_h16f[0][dir][mb][kt][lane][slot] = v;
    }
    if (idx < Cq * D2H)
        d_S1Wh[idx / D2H][idx % D2H] = __float2half(S1W[idx]);
    if (idx < 2 * G4H * Hq) {
        int dir = idx / (G4H * Hq);
        int r   = idx % (G4H * Hq);
        d_Wh16[dir][r / Hq][r % Hq] = __float2half((dir ? Whh_b : Whh_f)[r]);
    }
}

// ---------------- gather tokens + emb -> fp16 ----------------------------------
__global__ void gather_convert(const int* __restrict__ s1, const int* __restrict__ s2,
                               const float* __restrict__ emb) {
    int idx = blockIdx.x * blockDim.x + threadIdx.x;
    if (idx >= NROWS * KE) return;
    int m = idx / KE, k = idx % KE;
    int tok = (m < RPS) ? s1[m] : s2[m - RPS];
    d_xh16[m][k] = __float2half((k < Eq) ? emb[(long)tok * Eq + k] : 0.f);
}

// ---------------- Wih (both dirs) -> fp16 + combined bias ----------------------
__global__ void convert_wih(const float* __restrict__ Wih_f, const float* __restrict__ Wih_b,
                            const float* __restrict__ b_f, const float* __restrict__ b_b) {
    int idx = blockIdx.x * blockDim.x + threadIdx.x;
    if (idx >= 2 * G4H * KE) return;
    int n = idx / KE, k = idx % KE;
    int dir = n >> 11, nn = n & 2047;
    const float* W = dir ? Wih_b : Wih_f;
    d_Wih16[n][k] = __float2half((k < Eq) ? W[(long)nn * Eq + k] : 0.f);
    if (k == 0) d_biasC[n] = (dir ? b_b : b_f)[nn];
}

// ---------------- mma.sync helper -----------------------------------------------
__device__ __forceinline__ void mma_f16(float* d, const uint32_t* a, const uint32_t* b) {
    asm volatile(
        "mma.sync.aligned.m16n8k16.row.col.f32.f16.f16.f32 "
        "{%0,%1,%2,%3}, {%4,%5,%6,%7}, {%8,%9}, {%0,%1,%2,%3};\n"
        : "+f"(d[0]), "+f"(d[1]), "+f"(d[2]), "+f"(d[3])
        : "r"(a[0]), "r"(a[1]), "r"(a[2]), "r"(a[3]),
          "r"(b[0]), "r"(b[1]));
}

// ---------------- xW via fp16 tensor cores, k-pipelined -------------------------
__global__ __launch_bounds__(256)
void xw_mma() {
    const int lane = threadIdx.x & 31;
    const int warp = threadIdx.x >> 5;
    const int wm = warp & 1, wn = warp >> 1;
    const int m0 = blockIdx.y * 64 + wm * 32;
    const int n0 = blockIdx.x * 256 + wn * 64;
    const int RS = KE / 2;
    const int kc = lane & 3;
    const int rr = lane >> 2;
    const int KT = KE / 16;                 // 19

    const uint32_t* X = (const uint32_t*)&d_xh16[0][0];
    const uint32_t* W = (const uint32_t*)&d_Wih16[0][0];

    float acc[2][8][4] = {};
    uint32_t aF[2][2][4];      // [buf][mt][4]
    uint32_t bF[2][8][2];      // [buf][nt][2]

#define LD_TILE(buf, ktv) {                                                       \
        const int k0 = (ktv) * 8;                                                 \
        _Pragma("unroll")                                                         \
        for (int mt = 0; mt < 2; ++mt) {                                          \
            int base = (m0 + mt * 16 + rr) * RS + k0 + kc;                        \
            aF[buf][mt][0] = X[base];       aF[buf][mt][1] = X[base + 8 * RS];    \
            aF[buf][mt][2] = X[base + 4];   aF[buf][mt][3] = X[base + 8 * RS + 4];\
        }                                                                          \
        _Pragma("unroll")                                                         \
        for (int nt = 0; nt < 8; ++nt) {                                          \
            int bb = (n0 + nt * 8 + rr) * RS + k0 + kc;                           \
            bF[buf][nt][0] = W[bb];  bF[buf][nt][1] = W[bb + 4];                  \
        }                                                                          \
    }

    LD_TILE(0, 0);
    for (int kt = 0; kt < KT; ++kt) {
        const int cur = kt & 1;
        if (kt + 1 < KT) LD_TILE(cur ^ 1, kt + 1);
#pragma unroll
        for (int nt = 0; nt < 8; ++nt)
#pragma unroll
            for (int mt = 0; mt < 2; ++mt)
                mma_f16(acc[mt][nt], aF[cur][mt], bF[cur][nt]);
    }
#undef LD_TILE

#pragma unroll
    for (int mt = 0; mt < 2; ++mt)
#pragma unroll
        for (int nt = 0; nt < 8; ++nt) {
            int r  = m0 + mt * 16 + rr;
            int cc = n0 + nt * 8 + (lane & 3) * 2;
#pragma unroll
            for (int i = 0; i < 4; ++i) {
                int m = r + (i >> 1) * 8;
                int n = cc + (i & 1);
                int dir = n >> 11, nn = n & 2047;
                int g = nn >> 9, j = nn & 511;
                d_xW[dir][m][(j >> 1) * 8 + g * 2 + (j & 1)] = acc[mt][nt][i] + d_biasC[n];
            }
        }
}

// ---------------- persistent LSTM: fp16 single-MMA, R14 flag barrier ------------
__global__ __launch_bounds__(256)
void lstm_persist(const int* __restrict__ s1_len, const int* __restrict__ s2_len,
                  const float* __restrict__ s1_c0, const float* __restrict__ s2_c0) {
    extern __shared__ uint32_t sWf[];   // 32KB: [g(4)][kt(32)][lane(32)][b0,b1]
    const int tid  = threadIdx.x;
    const int lane = tid & 31;
    const int warp = tid >> 5;
    const int dir  = blockIdx.x & 1;
    const int cta  = blockIdx.x >> 1;   // 0..63 within dir
    const int j0   = cta * 8;

    // ---- fragment-major fp16 weight fill (once) ----
    for (int i = tid; i < 4096; i += 256) {
        int g  = i >> 10;
        int kt = (i >> 5) & 31;
        int l  = i & 31;
        int n  = l >> 2;
        int k0 = kt * 16 + (l & 3) * 2;
        const uint32_t* src = (const uint32_t*)&d_Wh16[dir][g * Hq + j0 + n][0];
        uint2 v;
        v.x = src[k0 >> 1];
        v.y = src[(k0 + 8) >> 1];
        *(uint2*)&sWf[i * 2] = v;
    }

    // ---- per-thread ownership ----
    const int m0  = warp * 16;
    const int seq = m0 >> 6;
    const int r0  = m0 + (lane >> 2);
    const int c0j = j0 + (lane & 3) * 2;
    const int*   lens = seq ? s2_len : s1_len;
    const float* c0p  = seq ? s2_c0  : s1_c0;
    const int b0 = r0 & 63;
    const int len_[2] = { lens[b0], lens[b0 + 8] };
    const int ktW   = j0 >> 4;
    const int kslot = (j0 >> 3) & 1;

    float creg[4];
#pragma unroll
    for (int ri = 0; ri < 2; ++ri)
#pragma unroll
        for (int ci = 0; ci < 2; ++ci)
            creg[ri * 2 + ci] = c0p[(dir * Bq + b0 + 8 * ri) * Hq + c0j + ci];

    __syncthreads();

    unsigned myep = 0;

    // ---- prefetch xW for step 0 ----
    int rowx_[2];
    float4 pa[2], pb[2];
#pragma unroll
    for (int ri = 0; ri < 2; ++ri) {
        int b = b0 + 8 * ri;
        int len = len_[ri];
        int tpos = dir ? (len - 1) : 0;
        rowx_[ri] = (seq * Bq + b) * Tq + tpos;
        const float4* x4 = (const float4*)&d_xW[dir][rowx_[ri]][(c0j >> 1) * 8];
        pa[ri] = __ldcs(x4);
        pb[ri] = __ldcs(x4 + 1);
    }

    for (int t = 0; t < Tq; ++t) {
        const int p = t & 1;
        const uint32_t* HF = &d_h16f[p][dir][warp][0][0][0];

        float acc[4][4] = {};
        uint32_t aF[5][4];

#define LOADA(buf, ktv) {                                                         \
        uint4 vh = __ldcg((const uint4*)(HF + (ktv) * 128 + lane * 4));           \
        aF[buf][0] = vh.x; aF[buf][1] = vh.y; aF[buf][2] = vh.z; aF[buf][3] = vh.w; }

        LOADA(0, 0); LOADA(1, 1); LOADA(2, 2); LOADA(3, 3);

#pragma unroll
        for (int kt = 0; kt < 32; ++kt) {
            const int cur = kt % 5;
            if (kt < 28) { LOADA((kt + 4) % 5, kt + 4); }
#pragma unroll
            for (int g = 0; g < 4; ++g) {
                uint2 wv = *(const uint2*)&sWf[((g * 32 + kt) * 32 + lane) * 2];
                uint32_t bF[2] = { wv.x, wv.y };
                mma_f16(acc[g], aF[cur], bF);
            }
        }
#undef LOADA

        // ---- epilogue: gates, cell/h update ----
        uint32_t hh[2];
#pragma unroll
        for (int ri = 0; ri < 2; ++ri) {
            float hv[2];
            {
                float gi = acc[0][ri * 2 + 0] + pa[ri].x;
                float gf = acc[1][ri * 2 + 0] + pa[ri].z;
                float gg = acc[2][ri * 2 + 0] + pb[ri].x;
                float go = acc[3][ri * 2 + 0] + pb[ri].z;
                float c  = fsigmoid(gf) * creg[ri * 2 + 0] + fsigmoid(gi) * ftanh(gg);
                hv[0]    = fsigmoid(go) * ftanh(c);
                creg[ri * 2 + 0] = c;
            }
            {
                float gi = acc[0][ri * 2 + 1] + pa[ri].y;
                float gf = acc[1][ri * 2 + 1] + pa[ri].w;
                float gg = acc[2][ri * 2 + 1] + pb[ri].y;
                float go = acc[3][ri * 2 + 1] + pb[ri].w;
                float c  = fsigmoid(gf) * creg[ri * 2 + 1] + fsigmoid(gi) * ftanh(gg);
                hv[1]    = fsigmoid(go) * ftanh(c);
                creg[ri * 2 + 1] = c;
            }
            hh[ri] = pack2h(hv[0], hv[1]);
        }
        // publish h state (fp16) FIRST: one STG.64
        *(uint2*)&d_h16f[p ^ 1][dir][warp][ktW][lane][kslot * 2] = make_uint2(hh[0], hh[1]);

        // ---- barrier arrive: parallel flag store ----
        __syncthreads();
        if (tid == 0) {
            __threadfence();
            *(volatile unsigned*)&d_flags[dir][cta] = myep + 1;
        }

        // ---- overlapped with barrier: Hof + next xW prefetch ----
#pragma unroll
        for (int ri = 0; ri < 2; ++ri)
            *(uint32_t*)&d_Hof[rowx_[ri]][dir * Hq + c0j] = hh[ri];
        int nrowx[2];
        float4 npa[2], npb[2];
        if (t + 1 < Tq) {
            const int tn = t + 1;
#pragma unroll
            for (int ri = 0; ri < 2; ++ri) {
                int b = b0 + 8 * ri;
                int len = len_[ri];
                int tpos = dir ? ((tn < len) ? (len - 1 - tn) : tn) : tn;
                nrowx[ri] = (seq * Bq + b) * Tq + tpos;
                const float4* x4 = (const float4*)&d_xW[dir][nrowx[ri]][(c0j >> 1) * 8];
                npa[ri] = __ldcs(x4);
                npb[ri] = __ldcs(x4 + 1);
            }
        }

        // ---- barrier wait ----
        if (cta == 0) {
            if (tid < 64) {
                while (*(volatile unsigned*)&d_flags[dir][tid] <= myep) { }
            }
            __syncthreads();
            if (tid == 0) {
                __threadfence();
                atomicExch(&g_epoch2[dir], myep + 1);
            }
        } else {
            if (tid == 0) {
                while (*(volatile unsigned*)&g_epoch2[dir] <= myep) { }
                __threadfence();
            }
        }
        myep++;
        __syncthreads();

        if (t + 1 < Tq) {
#pragma unroll
            for (int ri = 0; ri < 2; ++ri) {
                rowx_[ri] = nrowx[ri];
                pa[ri] = npa[ri];
                pb[ri] = npb[ri];
            }
        }
    }
}

// ---------------- attention projection: fp16 single-MMA, k-pipelined ------------
__global__ __launch_bounds__(256)
void attn_mma() {
    const int lane = threadIdx.x & 31;
    const int warp = threadIdx.x >> 5;
    const int wm = warp & 1, wn = warp >> 1;
    const int m0 = blockIdx.y * 64 + wm * 32;
    const int n0 = wn * 64;
    const int RS = D2H / 2;
    const int kc = lane & 3;
    const int rr = lane >> 2;
    const int KT = D2H / 16;               // 64

    const uint32_t* X = (const uint32_t*)&d_Hof[0][0];
    const uint32_t* W = (const uint32_t*)&d_S1Wh[0][0];

    float acc[2][8][4] = {};
    uint32_t aF[2][2][4];
    uint32_t bF[2][8][2];

#define LD_TILE(buf, ktv) {                                                       \
        const int k0 = (ktv) * 8;                                                 \
        _Pragma("unroll")                                                         \
        for (int mt = 0; mt < 2; ++mt) {                                          \
            int base = (m0 + mt * 16 + rr) * RS + k0 + kc;                        \
            aF[buf][mt][0] = X[base];       aF[buf][mt][1] = X[base + 8 * RS];    \
            aF[buf][mt][2] = X[base + 4];   aF[buf][mt][3] = X[base + 8 * RS + 4];\
        }                                                                          \
        _Pragma("unroll")                                                         \
        for (int nt = 0; nt < 8; ++nt) {                                          \
            int bb = (n0 + nt * 8 + rr) * RS + k0 + kc;                           \
            bF[buf][nt][0] = W[bb];  bF[buf][nt][1] = W[bb + 4];                  \
        }                                                                          \
    }

    LD_TILE(0, 0);
    for (int kt = 0; kt < KT; ++kt) {
        const int cur = kt & 1;
        if (kt + 1 < KT) LD_TILE(cur ^ 1, kt + 1);
#pragma unroll
        for (int nt = 0; nt < 8; ++nt)
#pragma unroll
            for (int mt = 0; mt < 2; ++mt)
                mma_f16(acc[mt][nt], aF[cur][mt], bF[cur][nt]);
    }
#undef LD_TILE

#pragma unroll
    for (int mt = 0; mt < 2; ++mt)
#pragma unroll
        for (int nt = 0; nt < 8; ++nt) {
            int r  = m0 + mt * 16 + rr;
            int cc = n0 + nt * 8 + (lane & 3) * 2;
#pragma unroll
            for (int i = 0; i < 4; ++i)
                d_P[r + (i >> 1) * 8][cc + (i & 1)] = acc[mt][nt][i];
        }
}

// ---------------- masked softmax attention pooling (fp16 h) ---------------------
__global__ __launch_bounds__(128)
void attn_pool(const int* __restrict__ s1_len, const int* __restrict__ s2_len,
               const float* __restrict__ S2W) {
    __shared__ float sS2[Cq];
    __shared__ float ssc[Tq];
    __shared__ float red[Tq];
    int sb = blockIdx.x;
    int seq = sb >> 6, b = sb & 63;
    int t = threadIdx.x;
    for (int c = t; c < Cq; c += Tq) sS2[c] = S2W[c];
    __syncthreads();

    long row = (long)sb * Tq + t;
    float s = 0.f;
    for (int c = 0; c < Cq; ++c) s += ftanh(d_P[row][c]) * sS2[c];
    int len = (seq ? s2_len : s1_len)[b];
    ssc[t] = (t < len) ? s : -1e9f;
    __syncthreads();

    red[t] = ssc[t]; __syncthreads();
    for (int o = 64; o > 0; o >>= 1) { if (t < o) red[t] = fmaxf(red[t], red[t + o]); __syncthreads(); }
    float mx = red[0]; __syncthreads();
    float ex = expf(ssc[t] - mx);
    red[t] = ex; __syncthreads();
    for (int o = 64; o > 0; o >>= 1) { if (t < o) red[t] += red[t + o]; __syncthreads(); }
    float inv = 1.f / red[0];
    __syncthreads();
    ssc[t] = ex * inv;
    __syncthreads();

    long rowbase = (long)sb * Tq;
    for (int d2 = t; d2 < D2H / 2; d2 += Tq) {
        float acc0 = 0.f, acc1 = 0.f;
        for (int tt = 0; tt < Tq; ++tt) {
            long rw = rowbase + tt;
            __half2 h2 = *(const __half2*)&d_Hof[rw][d2 * 2];
            float2 hf = __half22float2(h2);
            float w = ssc[tt];
            acc0 += w * hf.x;
            acc1 += w * hf.y;
        }
        d_r[seq][b][d2 * 2]     = acc0;
        d_r[seq][b][d2 * 2 + 1] = acc1;
    }
}

// ---------------- final MLP head + sigmoid --------------------------------------
__global__ __launch_bounds__(512)
void final_mlp(const float* __restrict__ mlpW, const float* __restrict__ mlpb,
               const float* __restrict__ outW, const float* __restrict__ outb,
               float* __restrict__ out) {
    __shared__ float merged[4 * Hq];
    __shared__ float smlp[Mq];
    __shared__ float red[16];
    int b = blockIdx.x;
    int tid = threadIdx.x;

    for (int d = tid; d < 2 * D2H; d += Mq) {
        float v;
        if (d < D2H) v = d_r[0][b][d] + d_r[1][b][d];
        else { float df = d_r[0][b][d - D2H] - d_r[1][b][d - D2H]; v = df * df; }
        merged[d] = v;
    }
    __syncthreads();

    int warp = tid >> 5, lane = tid & 31;
    for (int m = warp * 32; m < warp * 32 + 32; ++m) {
        float p = 0.f;
        for (int d = lane; d < 4 * Hq; d += 32) p += merged[d] * mlpW[(long)m * 4 * Hq + d];
        for (int o = 16; o > 0; o >>= 1) p += __shfl_down_sync(0xffffffff, p, o);
        if (lane == 0) smlp[m] = p + mlpb[m];
    }
    __syncthreads();

    float p = smlp[tid] * outW[tid];
    for (int o = 16; o > 0; o >>= 1) p += __shfl_down_sync(0xffffffff, p, o);
    if (lane == 0) red[warp] = p;
    __syncthreads();
    if (tid == 0) {
        float l = outb[0];
        for (int w = 0; w < 16; ++w) l += red[w];
        out[b] = 1.f / (1.f + expf(-l));
    }
}

// ---------------- launch ----------------------------------------------------------
extern "C" void kernel_launch(void* const* d_in, const int* in_sizes, int n_in,
                              void* d_out, int out_size) {
    const int*   s1     = (const int*)d_in[0];
    const int*   s2     = (const int*)d_in[1];
    const int*   s1_len = (const int*)d_in[2];
    const int*   s2_len = (const int*)d_in[3];
    const float* s1_h0  = (const float*)d_in[4];
    const float* s1_c0  = (const float*)d_in[5];
    const float* s2_h0  = (const float*)d_in[6];
    const float* s2_c0  = (const float*)d_in[7];
    const float* emb    = (const float*)d_in[8];
    const float* Wih_f  = (const float*)d_in[9];
    const float* Whh_f  = (const float*)d_in[10];
    const float* b_f    = (const float*)d_in[11];
    const float* Wih_b  = (const float*)d_in[12];
    const float* Whh_b  = (const float*)d_in[13];
    const float* b_b    = (const float*)d_in[14];
    const float* S1W    = (const float*)d_in[15];
    const float* S2W    = (const float*)d_in[16];
    const float* mlpW   = (const float*)d_in[17];
    const float* mlpb   = (const float*)d_in[18];
    const float* outW   = (const float*)d_in[19];
    const float* outb   = (const float*)d_in[20];
    float* out = (float*)d_out;

    const int smem_lstm = 8192 * (int)sizeof(uint32_t);   // 32KB
    cudaFuncSetAttribute(lstm_persist, cudaFuncAttributeMaxDynamicSharedMemorySize, smem_lstm);

    prep_all<<<(2 * G4H * Hq + 255) / 256, 256>>>(s1_h0, s2_h0, Whh_f, Whh_b, S1W);
    gather_convert<<<(NROWS * KE + 255) / 256, 256>>>(s1, s2, emb);
    convert_wih<<<(2 * G4H * KE + 255) / 256, 256>>>(Wih_f, Wih_b, b_f, b_b);

    xw_mma<<<dim3(16, 256), 256>>>();

    lstm_persist<<<NCTA, 256, smem_lstm>>>(s1_len, s2_len, s1_c0, s2_c0);

    attn_mma<<<dim3(1, 256), 256>>>();
    attn_pool<<<128, 128>>>(s1_len, s2_len, S2W);
    final_mlp<<<Bq, 512>>>(mlpW, mlpb, outW, outb, out);
}

// round 17
// speedup vs baseline: 1.1940x; 1.1940x over previous
#include <cuda_runtime.h>
#include <cuda_bf16.h>
#include <cuda_fp16.h>
#include <stdint.h>
#include <math.h>

// Problem constants
#define Bq   64
#define Tq   128
#define Eq   300
#define Hq   512
#define Cq   256
#define Mq   512
#define RPS  (Bq*Tq)      // 8192
#define NROWS (2*RPS)     // 16384
#define G4H  (4*Hq)       // 2048
#define D2H  (2*Hq)       // 1024
#define NCTA 128          // 64 per direction
#define KE   304

// -------- scratch ------------------------------------------------------------
__device__ float d_xW[2][NROWS][G4H];    // gate-interleaved [(j>>1)*8 + g*2 + (j&1)]
__device__ float d_P[NROWS][Cq];
__device__ float d_r[2][Bq][D2H];
__device__ __half d_Wh16[2][G4H][Hq];                // fp16 Whh
// h state (fp16) in mma-A-fragment-major layout:
// [parity][dir][mblock(8)][ktile(32)][lane(32)][slot(4)]  (u32 = half2)
__device__ uint32_t d_h16f[2][2][8][32][32][4];
__device__ __half d_xh16[NROWS][KE];                 // fp16 gathered embeddings
__device__ __half d_Wih16[2*G4H][KE];                // fp16 Wih (both dirs)
__device__ float d_biasC[2*G4H];
__device__ __half d_Hof[NROWS][D2H];                 // fp16 Hout (attn path)
__device__ __half d_S1Wh[Cq][D2H];                   // fp16 S1W
__device__ unsigned d_flags[2][64];                  // per-CTA arrive flags
__device__ unsigned g_epoch2[2];

// ---- helpers -----------------------------------------------------------------
__device__ __forceinline__ float fsigmoid(float x) { return __fdividef(1.f, 1.f + __expf(-x)); }
__device__ __forceinline__ float ftanh(float x)    { return 1.f - __fdividef(2.f, 1.f + __expf(2.f * x)); }
__device__ __forceinline__ uint32_t pack2h(float a, float b) {
    __half2 h = __floats2half2_rn(a, b);
    return *(uint32_t*)&h;
}

// ---------------- fused preamble: flags, h0 seed, Whh/S1W fp16 -----------------
__global__ void prep_all(const float* __restrict__ s1_h0, const float* __restrict__ s2_h0,
                         const float* __restrict__ Whh_f, const float* __restrict__ Whh_b,
                         const float* __restrict__ S1W) {
    int idx = blockIdx.x * blockDim.x + threadIdx.x;
    if (idx < 2) g_epoch2[idx] = 0;
    if (idx < 128) d_flags[idx >> 6][idx & 63] = 0;
    if (idx < 2 * 128 * (Hq / 2)) {
        int jj  = idx % (Hq / 2);
        int j   = jj * 2;
        int m   = (idx / (Hq / 2)) % 128;
        int dir = idx / ((Hq / 2) * 128);
        int seq = m >> 6, b = m & 63;
        const float* h0 = seq ? s2_h0 : s1_h0;
        uint32_t v = pack2h(h0[(dir * Bq + b) * Hq + j], h0[(dir * Bq + b) * Hq + j + 1]);
        int mb   = m >> 4;
        int kt   = j >> 4;
        int lane = (m & 7) * 4 + ((j >> 1) & 3);
        int slot = ((j & 15) >> 3) * 2 + ((m & 15) >> 3);
        d_h16f[0][dir][mb][kt][lane][slot] = v;
    }
    if (idx < Cq * D2H)
        d_S1Wh[idx / D2H][idx % D2H] = __float2half(S1W[idx]);
    if (idx < 2 * G4H * Hq) {
        int dir = idx / (G4H * Hq);
        int r   = idx % (G4H * Hq);
        d_Wh16[dir][r / Hq][r % Hq] = __float2half((dir ? Whh_b : Whh_f)[r]);
    }
}

// ---------------- gather tokens + emb -> fp16 ----------------------------------
__global__ void gather_convert(const int* __restrict__ s1, const int* __restrict__ s2,
                               const float* __restrict__ emb) {
    int idx = blockIdx.x * blockDim.x + threadIdx.x;
    if (idx >= NROWS * KE) return;
    int m = idx / KE, k = idx % KE;
    int tok = (m < RPS) ? s1[m] : s2[m - RPS];
    d_xh16[m][k] = __float2half((k < Eq) ? emb[(long)tok * Eq + k] : 0.f);
}

// ---------------- Wih (both dirs) -> fp16 + combined bias ----------------------
__global__ void convert_wih(const float* __restrict__ Wih_f, const float* __restrict__ Wih_b,
                            const float* __restrict__ b_f, const float* __restrict__ b_b) {
    int idx = blockIdx.x * blockDim.x + threadIdx.x;
    if (idx >= 2 * G4H * KE) return;
    int n = idx / KE, k = idx % KE;
    int dir = n >> 11, nn = n & 2047;
    const float* W = dir ? Wih_b : Wih_f;
    d_Wih16[n][k] = __float2half((k < Eq) ? W[(long)nn * Eq + k] : 0.f);
    if (k == 0) d_biasC[n] = (dir ? b_b : b_f)[nn];
}

// ---------------- mma.sync helper -----------------------------------------------
__device__ __forceinline__ void mma_f16(float* d, const uint32_t* a, const uint32_t* b) {
    asm volatile(
        "mma.sync.aligned.m16n8k16.row.col.f32.f16.f16.f32 "
        "{%0,%1,%2,%3}, {%4,%5,%6,%7}, {%8,%9}, {%0,%1,%2,%3};\n"
        : "+f"(d[0]), "+f"(d[1]), "+f"(d[2]), "+f"(d[3])
        : "r"(a[0]), "r"(a[1]), "r"(a[2]), "r"(a[3]),
          "r"(b[0]), "r"(b[1]));
}

// ---------------- xW via fp16 tensor cores, static double-buffer ----------------
__global__ __launch_bounds__(256)
void xw_mma() {
    const int lane = threadIdx.x & 31;
    const int warp = threadIdx.x >> 5;
    const int wm = warp & 1, wn = warp >> 1;
    const int m0 = blockIdx.y * 64 + wm * 32;
    const int n0 = blockIdx.x * 256 + wn * 64;
    const int RS = KE / 2;
    const int kc = lane & 3;
    const int rr = lane >> 2;

    const uint32_t* X = (const uint32_t*)&d_xh16[0][0];
    const uint32_t* W = (const uint32_t*)&d_Wih16[0][0];

    float acc[2][8][4] = {};
    // STATIC buffer names — never dynamically indexed, guaranteed registers
    uint32_t aF0[2][4], aF1[2][4], bF0[8][2], bF1[8][2];

#define LD_T(aF, bF, ktv) {                                                       \
        const int k0 = (ktv) * 8;                                                 \
        _Pragma("unroll")                                                         \
        for (int mt = 0; mt < 2; ++mt) {                                          \
            int base = (m0 + mt * 16 + rr) * RS + k0 + kc;                        \
            aF[mt][0] = X[base];       aF[mt][1] = X[base + 8 * RS];              \
            aF[mt][2] = X[base + 4];   aF[mt][3] = X[base + 8 * RS + 4];          \
        }                                                                          \
        _Pragma("unroll")                                                         \
        for (int nt = 0; nt < 8; ++nt) {                                          \
            int bb = (n0 + nt * 8 + rr) * RS + k0 + kc;                           \
            bF[nt][0] = W[bb];  bF[nt][1] = W[bb + 4];                            \
        }                                                                          \
    }
#define MMA_T(aF, bF) {                                                            \
        _Pragma("unroll")                                                         \
        for (int nt = 0; nt < 8; ++nt)                                            \
            _Pragma("unroll")                                                     \
            for (int mt = 0; mt < 2; ++mt)                                        \
                mma_f16(acc[mt][nt], aF[mt], bF[nt]);                             \
    }

    LD_T(aF0, bF0, 0);
    // KT = 19: pairs (0..17), tail tile 18
    for (int kt = 0; kt < 18; kt += 2) {
        LD_T(aF1, bF1, kt + 1);
        MMA_T(aF0, bF0);
        LD_T(aF0, bF0, kt + 2);     // kt+2 <= 18, always valid
        MMA_T(aF1, bF1);
    }
    MMA_T(aF0, bF0);                 // tile 18
#undef LD_T
#undef MMA_T

#pragma unroll
    for (int mt = 0; mt < 2; ++mt)
#pragma unroll
        for (int nt = 0; nt < 8; ++nt) {
            int r  = m0 + mt * 16 + rr;
            int cc = n0 + nt * 8 + (lane & 3) * 2;
#pragma unroll
            for (int i = 0; i < 4; ++i) {
                int m = r + (i >> 1) * 8;
                int n = cc + (i & 1);
                int dir = n >> 11, nn = n & 2047;
                int g = nn >> 9, j = nn & 511;
                d_xW[dir][m][(j >> 1) * 8 + g * 2 + (j & 1)] = acc[mt][nt][i] + d_biasC[n];
            }
        }
}

// ---------------- persistent LSTM: fp16 single-MMA, R14 flag barrier ------------
__global__ __launch_bounds__(256)
void lstm_persist(const int* __restrict__ s1_len, const int* __restrict__ s2_len,
                  const float* __restrict__ s1_c0, const float* __restrict__ s2_c0) {
    extern __shared__ uint32_t sWf[];   // 32KB: [g(4)][kt(32)][lane(32)][b0,b1]
    const int tid  = threadIdx.x;
    const int lane = tid & 31;
    const int warp = tid >> 5;
    const int dir  = blockIdx.x & 1;
    const int cta  = blockIdx.x >> 1;
    const int j0   = cta * 8;

    for (int i = tid; i < 4096; i += 256) {
        int g  = i >> 10;
        int kt = (i >> 5) & 31;
        int l  = i & 31;
        int n  = l >> 2;
        int k0 = kt * 16 + (l & 3) * 2;
        const uint32_t* src = (const uint32_t*)&d_Wh16[dir][g * Hq + j0 + n][0];
        uint2 v;
        v.x = src[k0 >> 1];
        v.y = src[(k0 + 8) >> 1];
        *(uint2*)&sWf[i * 2] = v;
    }

    const int m0  = warp * 16;
    const int seq = m0 >> 6;
    const int r0  = m0 + (lane >> 2);
    const int c0j = j0 + (lane & 3) * 2;
    const int*   lens = seq ? s2_len : s1_len;
    const float* c0p  = seq ? s2_c0  : s1_c0;
    const int b0 = r0 & 63;
    const int len_[2] = { lens[b0], lens[b0 + 8] };
    const int ktW   = j0 >> 4;
    const int kslot = (j0 >> 3) & 1;

    float creg[4];
#pragma unroll
    for (int ri = 0; ri < 2; ++ri)
#pragma unroll
        for (int ci = 0; ci < 2; ++ci)
            creg[ri * 2 + ci] = c0p[(dir * Bq + b0 + 8 * ri) * Hq + c0j + ci];

    __syncthreads();

    unsigned myep = 0;

    int rowx_[2];
    float4 pa[2], pb[2];
#pragma unroll
    for (int ri = 0; ri < 2; ++ri) {
        int b = b0 + 8 * ri;
        int len = len_[ri];
        int tpos = dir ? (len - 1) : 0;
        rowx_[ri] = (seq * Bq + b) * Tq + tpos;
        const float4* x4 = (const float4*)&d_xW[dir][rowx_[ri]][(c0j >> 1) * 8];
        pa[ri] = __ldcs(x4);
        pb[ri] = __ldcs(x4 + 1);
    }

    for (int t = 0; t < Tq; ++t) {
        const int p = t & 1;
        const uint32_t* HF = &d_h16f[p][dir][warp][0][0][0];

        float acc[4][4] = {};
        uint32_t aF[5][4];

#define LOADA(buf, ktv) {                                                         \
        uint4 vh = __ldcg((const uint4*)(HF + (ktv) * 128 + lane * 4));           \
        aF[buf][0] = vh.x; aF[buf][1] = vh.y; aF[buf][2] = vh.z; aF[buf][3] = vh.w; }

        LOADA(0, 0); LOADA(1, 1); LOADA(2, 2); LOADA(3, 3);

#pragma unroll
        for (int kt = 0; kt < 32; ++kt) {
            const int cur = kt % 5;
            if (kt < 28) { LOADA((kt + 4) % 5, kt + 4); }
#pragma unroll
            for (int g = 0; g < 4; ++g) {
                uint2 wv = *(const uint2*)&sWf[((g * 32 + kt) * 32 + lane) * 2];
                uint32_t bF[2] = { wv.x, wv.y };
                mma_f16(acc[g], aF[cur], bF);
            }
        }
#undef LOADA

        uint32_t hh[2];
#pragma unroll
        for (int ri = 0; ri < 2; ++ri) {
            float hv[2];
            {
                float gi = acc[0][ri * 2 + 0] + pa[ri].x;
                float gf = acc[1][ri * 2 + 0] + pa[ri].z;
                float gg = acc[2][ri * 2 + 0] + pb[ri].x;
                float go = acc[3][ri * 2 + 0] + pb[ri].z;
                float c  = fsigmoid(gf) * creg[ri * 2 + 0] + fsigmoid(gi) * ftanh(gg);
                hv[0]    = fsigmoid(go) * ftanh(c);
                creg[ri * 2 + 0] = c;
            }
            {
                float gi = acc[0][ri * 2 + 1] + pa[ri].y;
                float gf = acc[1][ri * 2 + 1] + pa[ri].w;
                float gg = acc[2][ri * 2 + 1] + pb[ri].y;
                float go = acc[3][ri * 2 + 1] + pb[ri].w;
                float c  = fsigmoid(gf) * creg[ri * 2 + 1] + fsigmoid(gi) * ftanh(gg);
                hv[1]    = fsigmoid(go) * ftanh(c);
                creg[ri * 2 + 1] = c;
            }
            hh[ri] = pack2h(hv[0], hv[1]);
        }
        *(uint2*)&d_h16f[p ^ 1][dir][warp][ktW][lane][kslot * 2] = make_uint2(hh[0], hh[1]);

        __syncthreads();
        if (tid == 0) {
            __threadfence();
            *(volatile unsigned*)&d_flags[dir][cta] = myep + 1;
        }

#pragma unroll
        for (int ri = 0; ri < 2; ++ri)
            *(uint32_t*)&d_Hof[rowx_[ri]][dir * Hq + c0j] = hh[ri];
        int nrowx[2];
        float4 npa[2], npb[2];
        if (t + 1 < Tq) {
            const int tn = t + 1;
#pragma unroll
            for (int ri = 0; ri < 2; ++ri) {
                int b = b0 + 8 * ri;
                int len = len_[ri];
                int tpos = dir ? ((tn < len) ? (len - 1 - tn) : tn) : tn;
                nrowx[ri] = (seq * Bq + b) * Tq + tpos;
                const float4* x4 = (const float4*)&d_xW[dir][nrowx[ri]][(c0j >> 1) * 8];
                npa[ri] = __ldcs(x4);
                npb[ri] = __ldcs(x4 + 1);
            }
        }

        if (cta == 0) {
            if (tid < 64) {
                while (*(volatile unsigned*)&d_flags[dir][tid] <= myep) { }
            }
            __syncthreads();
            if (tid == 0) {
                __threadfence();
                atomicExch(&g_epoch2[dir], myep + 1);
            }
        } else {
            if (tid == 0) {
                while (*(volatile unsigned*)&g_epoch2[dir] <= myep) { }
                __threadfence();
            }
        }
        myep++;
        __syncthreads();

        if (t + 1 < Tq) {
#pragma unroll
            for (int ri = 0; ri < 2; ++ri) {
                rowx_[ri] = nrowx[ri];
                pa[ri] = npa[ri];
                pb[ri] = npb[ri];
            }
        }
    }
}

// ---------------- attention projection: fp16, static double-buffer --------------
__global__ __launch_bounds__(256)
void attn_mma() {
    const int lane = threadIdx.x & 31;
    const int warp = threadIdx.x >> 5;
    const int wm = warp & 1, wn = warp >> 1;
    const int m0 = blockIdx.y * 64 + wm * 32;
    const int n0 = wn * 64;
    const int RS = D2H / 2;
    const int kc = lane & 3;
    const int rr = lane >> 2;

    const uint32_t* X = (const uint32_t*)&d_Hof[0][0];
    const uint32_t* W = (const uint32_t*)&d_S1Wh[0][0];

    float acc[2][8][4] = {};
    uint32_t aF0[2][4], aF1[2][4], bF0[8][2], bF1[8][2];

#define LD_T(aF, bF, ktv) {                                                       \
        const int k0 = (ktv) * 8;                                                 \
        _Pragma("unroll")                                                         \
        for (int mt = 0; mt < 2; ++mt) {                                          \
            int base = (m0 + mt * 16 + rr) * RS + k0 + kc;                        \
            aF[mt][0] = X[base];       aF[mt][1] = X[base + 8 * RS];              \
            aF[mt][2] = X[base + 4];   aF[mt][3] = X[base + 8 * RS + 4];          \
        }                                                                          \
        _Pragma("unroll")                                                         \
        for (int nt = 0; nt < 8; ++nt) {                                          \
            int bb = (n0 + nt * 8 + rr) * RS + k0 + kc;                           \
            bF[nt][0] = W[bb];  bF[nt][1] = W[bb + 4];                            \
        }                                                                          \
    }
#define MMA_T(aF, bF) {                                                            \
        _Pragma("unroll")                                                         \
        for (int nt = 0; nt < 8; ++nt)                                            \
            _Pragma("unroll")                                                     \
            for (int mt = 0; mt < 2; ++mt)                                        \
                mma_f16(acc[mt][nt], aF[mt], bF[nt]);                             \
    }

    LD_T(aF0, bF0, 0);
    // KT = 64 (even): pairs only, no tail
    for (int kt = 0; kt < 64; kt += 2) {
        LD_T(aF1, bF1, kt + 1);
        MMA_T(aF0, bF0);
        if (kt + 2 < 64) LD_T(aF0, bF0, kt + 2);
        MMA_T(aF1, bF1);
    }
#undef LD_T
#undef MMA_T

#pragma unroll
    for (int mt = 0; mt < 2; ++mt)
#pragma unroll
        for (int nt = 0; nt < 8; ++nt) {
            int r  = m0 + mt * 16 + rr;
            int cc = n0 + nt * 8 + (lane & 3) * 2;
#pragma unroll
            for (int i = 0; i < 4; ++i)
                d_P[r + (i >> 1) * 8][cc + (i & 1)] = acc[mt][nt][i];
        }
}

// ---------------- masked softmax attention pooling (fp16 h) ---------------------
__global__ __launch_bounds__(128)
void attn_pool(const int* __restrict__ s1_len, const int* __restrict__ s2_len,
               const float* __restrict__ S2W) {
    __shared__ float sS2[Cq];
    __shared__ float ssc[Tq];
    __shared__ float red[Tq];
    int sb = blockIdx.x;
    int seq = sb >> 6, b = sb & 63;
    int t = threadIdx.x;
    for (int c = t; c < Cq; c += Tq) sS2[c] = S2W[c];
    __syncthreads();

    long row = (long)sb * Tq + t;
    float s = 0.f;
    for (int c = 0; c < Cq; ++c) s += ftanh(d_P[row][c]) * sS2[c];
    int len = (seq ? s2_len : s1_len)[b];
    ssc[t] = (t < len) ? s : -1e9f;
    __syncthreads();

    red[t] = ssc[t]; __syncthreads();
    for (int o = 64; o > 0; o >>= 1) { if (t < o) red[t] = fmaxf(red[t], red[t + o]); __syncthreads(); }
    float mx = red[0]; __syncthreads();
    float ex = expf(ssc[t] - mx);
    red[t] = ex; __syncthreads();
    for (int o = 64; o > 0; o >>= 1) { if (t < o) red[t] += red[t + o]; __syncthreads(); }
    float inv = 1.f / red[0];
    __syncthreads();
    ssc[t] = ex * inv;
    __syncthreads();

    long rowbase = (long)sb * Tq;
    for (int d2 = t; d2 < D2H / 2; d2 += Tq) {
        float acc0 = 0.f, acc1 = 0.f;
        for (int tt = 0; tt < Tq; ++tt) {
            long rw = rowbase + tt;
            __half2 h2 = *(const __half2*)&d_Hof[rw][d2 * 2];
            float2 hf = __half22float2(h2);
            float w = ssc[tt];
            acc0 += w * hf.x;
            acc1 += w * hf.y;
        }
        d_r[seq][b][d2 * 2]     = acc0;
        d_r[seq][b][d2 * 2 + 1] = acc1;
    }
}

// ---------------- final MLP head + sigmoid --------------------------------------
__global__ __launch_bounds__(512)
void final_mlp(const float* __restrict__ mlpW, const float* __restrict__ mlpb,
               const float* __restrict__ outW, const float* __restrict__ outb,
               float* __restrict__ out) {
    __shared__ float merged[4 * Hq];
    __shared__ float smlp[Mq];
    __shared__ float red[16];
    int b = blockIdx.x;
    int tid = threadIdx.x;

    for (int d = tid; d < 2 * D2H; d += Mq) {
        float v;
        if (d < D2H) v = d_r[0][b][d] + d_r[1][b][d];
        else { float df = d_r[0][b][d - D2H] - d_r[1][b][d - D2H]; v = df * df; }
        merged[d] = v;
    }
    __syncthreads();

    int warp = tid >> 5, lane = tid & 31;
    for (int m = warp * 32; m < warp * 32 + 32; ++m) {
        float p = 0.f;
        for (int d = lane; d < 4 * Hq; d += 32) p += merged[d] * mlpW[(long)m * 4 * Hq + d];
        for (int o = 16; o > 0; o >>= 1) p += __shfl_down_sync(0xffffffff, p, o);
        if (lane == 0) smlp[m] = p + mlpb[m];
    }
    __syncthreads();

    float p = smlp[tid] * outW[tid];
    for (int o = 16; o > 0; o >>= 1) p += __shfl_down_sync(0xffffffff, p, o);
    if (lane == 0) red[warp] = p;
    __syncthreads();
    if (tid == 0) {
        float l = outb[0];
        for (int w = 0; w < 16; ++w) l += red[w];
        out[b] = 1.f / (1.f + expf(-l));
    }
}

// ---------------- launch ----------------------------------------------------------
extern "C" void kernel_launch(void* const* d_in, const int* in_sizes, int n_in,
                              void* d_out, int out_size) {
    const int*   s1     = (const int*)d_in[0];
    const int*   s2     = (const int*)d_in[1];
    const int*   s1_len = (const int*)d_in[2];
    const int*   s2_len = (const int*)d_in[3];
    const float* s1_h0  = (const float*)d_in[4];
    const float* s1_c0  = (const float*)d_in[5];
    const float* s2_h0  = (const float*)d_in[6];
    const float* s2_c0  = (const float*)d_in[7];
    const float* emb    = (const float*)d_in[8];
    const float* Wih_f  = (const float*)d_in[9];
    const float* Whh_f  = (const float*)d_in[10];
    const float* b_f    = (const float*)d_in[11];
    const float* Wih_b  = (const float*)d_in[12];
    const float* Whh_b  = (const float*)d_in[13];
    const float* b_b    = (const float*)d_in[14];
    const float* S1W    = (const float*)d_in[15];
    const float* S2W    = (const float*)d_in[16];
    const float* mlpW   = (const float*)d_in[17];
    const float* mlpb   = (const float*)d_in[18];
    const float* outW   = (const float*)d_in[19];
    const float* outb   = (const float*)d_in[20];
    float* out = (float*)d_out;

    const int smem_lstm = 8192 * (int)sizeof(uint32_t);   // 32KB
    cudaFuncSetAttribute(lstm_persist, cudaFuncAttributeMaxDynamicSharedMemorySize, smem_lstm);

    prep_all<<<(2 * G4H * Hq + 255) / 256, 256>>>(s1_h0, s2_h0, Whh_f, Whh_b, S1W);
    gather_convert<<<(NROWS * KE + 255) / 256, 256>>>(s1, s2, emb);
    convert_wih<<<(2 * G4H * KE + 255) / 256, 256>>>(Wih_f, Wih_b, b_f, b_b);

    xw_mma<<<dim3(16, 256), 256>>>();

    lstm_persist<<<NCTA, 256, smem_lstm>>>(s1_len, s2_len, s1_c0, s2_c0);

    attn_mma<<<dim3(1, 256), 256>>>();
    attn_pool<<<128, 128>>>(s1_len, s2_len, S2W);
    final_mlp<<<Bq, 512>>>(mlpW, mlpb, outW, outb, out);
}